// round 8
// baseline (speedup 1.0000x reference)
#include <cuda_runtime.h>
#include <cuda_bf16.h>
#include <math.h>
#include <stdint.h>

// ---------------------------------------------------------------------------
// SmallMLP ternary forward, v5: HMMA (mma.sync bf16) GEMM1, exact 2-way split.
//   x = hi + lo  (bf16 pair: ~17 mantissa bits, residual 2^-18 -> negligible)
//   h = relu([hi|lo] @ [tern(w1)|tern(w1)]^T + b1)   (K_eff = 1568 = 49*32)
//   s = 127/max(h);  logits = (round(h*s) @ tern(w2)^T)/s + b2;  log_softmax
// NOTE: tcgen05 is unavailable (harness PTX target is compute_103, not 103a);
// mma.sync is the fastest tensor path that compiles at this target.
// ---------------------------------------------------------------------------

#define B_    8192
#define DIN   784
#define DH    4096
#define DOUT  10

#define KE    1568          // 2*784, 49 chunks of 32
#define NIT   49
#define BM    256
#define BN    128
#define BK    32
#define PITCH 80            // SMEM row pitch bytes (5*16B -> conflict-free ldmatrix)
#define A_STG (BM * PITCH)  // 20480
#define B_STG (BN * PITCH)  // 10240
#define STG_SZ (A_STG + B_STG)
#define NSTG  4
#define GSMEM (NSTG * STG_SZ)   // 122880 bytes

#define NSPL  16

// Scratch (device globals: allocation-free rule)
__device__ __nv_bfloat16 g_A[(size_t)B_ * KE];    // [m][k] split-stacked
__device__ __nv_bfloat16 g_Bw[(size_t)DH * KE];   // [n][k] ternary (duplicated halves)
__device__ float    g_hT2[(size_t)DH * B_];
__device__ int      g_slot[DH];
__device__ unsigned g_nzw2[DH];
__device__ int      g_nnzc;
__device__ float    g_logits[B_ * 16];
__device__ unsigned g_maxbits;

// ------------------------------ asm helpers -------------------------------
__device__ __forceinline__ uint32_t smem_u32(const void* p) {
    uint32_t a;
    asm("{ .reg .u64 t; cvta.to.shared.u64 t, %1; cvt.u32.u64 %0, t; }" : "=r"(a) : "l"(p));
    return a;
}
__device__ __forceinline__ void cp16(uint32_t dst, const void* src) {
    asm volatile("cp.async.cg.shared.global [%0], [%1], 16;" :: "r"(dst), "l"(src));
}
__device__ __forceinline__ void cp_commit() { asm volatile("cp.async.commit_group;" ::: "memory"); }
template<int N> __device__ __forceinline__ void cp_wait() {
    asm volatile("cp.async.wait_group %0;" :: "n"(N) : "memory");
}
__device__ __forceinline__ void ldm4(uint32_t* r, uint32_t addr) {
    asm volatile("ldmatrix.sync.aligned.m8n8.x4.shared.b16 {%0,%1,%2,%3}, [%4];"
                 : "=r"(r[0]), "=r"(r[1]), "=r"(r[2]), "=r"(r[3]) : "r"(addr));
}
__device__ __forceinline__ void mma_bf16(float* d, const uint32_t* a, uint32_t b0, uint32_t b1) {
    asm volatile("mma.sync.aligned.m16n8k16.row.col.f32.bf16.bf16.f32 "
                 "{%0,%1,%2,%3}, {%4,%5,%6,%7}, {%8,%9}, {%0,%1,%2,%3};"
                 : "+f"(d[0]), "+f"(d[1]), "+f"(d[2]), "+f"(d[3])
                 : "r"(a[0]), "r"(a[1]), "r"(a[2]), "r"(a[3]), "r"(b0), "r"(b1));
}

// ------------------------------ small kernels ------------------------------
__global__ void init_kernel() { g_maxbits = 0u; g_nnzc = 0; }

__global__ void l2init_kernel() { g_logits[blockIdx.x * 512 + threadIdx.x] = 0.0f; }

// x -> split-stacked bf16: k<784: hi(x[k]); k>=784: lo = bf16(x - hi)
__global__ void __launch_bounds__(256)
convert_x_kernel(const float* __restrict__ x) {
    int idx = blockIdx.x * 256 + threadIdx.x;          // over B_*KE
    int m = idx / KE;
    int k = idx - m * KE;
    int ks = (k < DIN) ? k : (k - DIN);
    float v = __ldg(x + (size_t)m * DIN + ks);
    __nv_bfloat16 h1 = __float2bfloat16(v);
    g_A[idx] = (k < DIN) ? h1 : __float2bfloat16(v - __bfloat162float(h1));
}

// w1 -> ternary bf16, duplicated across the two K halves
__global__ void __launch_bounds__(256)
convert_w1_kernel(const float* __restrict__ w1) {
    int idx = blockIdx.x * 256 + threadIdx.x;          // over DH*KE
    int n = idx / KE;
    int k = idx - n * KE;
    int ks = (k < DIN) ? k : (k - DIN);
    float w = __ldg(w1 + (size_t)n * DIN + ks);
    float t = (w > 0.1f) ? 1.0f : ((w < -0.1f) ? -1.0f : 0.0f);
    g_Bw[idx] = __float2bfloat16(t);
}

// Packed ternary COLUMNS of w2; compact the nonzero columns.
__global__ void build_w2col_kernel(const float* __restrict__ w2) {
    int n = blockIdx.x * 256 + threadIdx.x;
    if (n >= DH) return;
    unsigned cw = 0;
    #pragma unroll
    for (int o = 0; o < DOUT; o++) {
        float w = w2[(size_t)o * DH + n];
        if (w >  0.1f) cw |= 1u << o;
        if (w < -0.1f) cw |= 1u << (16 + o);
    }
    if (cw) {
        int p = atomicAdd(&g_nnzc, 1);
        g_nzw2[p] = cw;
        g_slot[n] = p;
    } else {
        g_slot[n] = -1;
    }
}

// ---------------------------------------------------------------------------
// HMMA GEMM: BM=256 x BN=128, BK=32, 512 threads (16 warps, warp tile 64x32),
// 4-stage cp.async pipeline, K loop = 49 iters over KE=1568.
// ---------------------------------------------------------------------------
__device__ __forceinline__ void load_stage(uint32_t sa, uint32_t sb, int j,
                                           int m0, int n0, int tid) {
    const char* Ag = (const char*)g_A;
    const char* Bg = (const char*)g_Bw;
    const size_t koff = (size_t)j * (BK * 2);          // 64 bytes per chunk
    #pragma unroll
    for (int it = 0; it < 2; it++) {                   // A: 1024 x 16B chunks
        int q = tid + it * 512;
        int r = q >> 2, c = q & 3;
        cp16(sa + r * PITCH + c * 16,
             Ag + (size_t)(m0 + r) * (KE * 2) + koff + c * 16);
    }
    {                                                  // B: 512 x 16B chunks
        int r = tid >> 2, c = tid & 3;
        cp16(sb + r * PITCH + c * 16,
             Bg + (size_t)(n0 + r) * (KE * 2) + koff + c * 16);
    }
}

__global__ void __launch_bounds__(512, 1)
gemm_mma_kernel(const float* __restrict__ b1) {
    extern __shared__ char smraw[];
    const uint32_t sbase = smem_u32(smraw);
    __shared__ int   slot_s[BN];
    __shared__ float b1_s[BN];

    const int tid  = threadIdx.x;
    const int lane = tid & 31;
    const int wid  = tid >> 5;
    const int wm   = wid & 3;       // 4 m-warps
    const int wn   = wid >> 2;      // 4 n-warps
    const int m0   = blockIdx.x * BM;
    const int n0   = blockIdx.y * BN;

    if (tid < BN) { slot_s[tid] = g_slot[n0 + tid]; b1_s[tid] = __ldg(b1 + n0 + tid); }

    // prologue: 3 stages in flight
    #pragma unroll
    for (int s = 0; s < 3; s++) {
        uint32_t st = sbase + s * STG_SZ;
        load_stage(st, st + A_STG, s, m0, n0, tid);
        cp_commit();
    }

    float acc[4][4][4];
    #pragma unroll
    for (int mi = 0; mi < 4; mi++)
        #pragma unroll
        for (int ni = 0; ni < 4; ni++)
            #pragma unroll
            for (int c = 0; c < 4; c++) acc[mi][ni][c] = 0.0f;

    const uint32_t a_off = (wm * 64 + (lane & 15)) * PITCH + (lane >> 4) * 16;
    const uint32_t b_off = (wn * 32 + (lane & 15)) * PITCH + (lane >> 4) * 16;

    for (int j = 0; j < NIT; j++) {
        if (j + 2 < NIT)      cp_wait<2>();
        else if (j + 1 < NIT) cp_wait<1>();
        else                  cp_wait<0>();
        __syncthreads();

        // issue next load early (buffer (j+3)%4 == (j-1)%4 is free past the barrier)
        if (j + 3 < NIT) {
            uint32_t st = sbase + ((j + 3) & 3) * STG_SZ;
            load_stage(st, st + A_STG, j + 3, m0, n0, tid);
            cp_commit();
        }

        const uint32_t sa = sbase + (j & 3) * STG_SZ;
        const uint32_t sb = sa + A_STG;

        #pragma unroll
        for (int ks = 0; ks < 2; ks++) {
            uint32_t af[4][4];
            #pragma unroll
            for (int mi = 0; mi < 4; mi++)
                ldm4(af[mi], sa + a_off + mi * 16 * PITCH + ks * 32);
            uint32_t bf0[4], bf1[4];
            ldm4(bf0, sb + b_off + ks * 32);
            ldm4(bf1, sb + b_off + 16 * PITCH + ks * 32);
            #pragma unroll
            for (int mi = 0; mi < 4; mi++) {
                mma_bf16(acc[mi][0], af[mi], bf0[0], bf0[2]);
                mma_bf16(acc[mi][1], af[mi], bf0[1], bf0[3]);
                mma_bf16(acc[mi][2], af[mi], bf1[0], bf1[2]);
                mma_bf16(acc[mi][3], af[mi], bf1[1], bf1[3]);
            }
        }
    }

    // ---- epilogue: bias + relu + global max + compacted transposed store
    float lmax = 0.0f;
    const int mb = m0 + wm * 64;
    const int nb = wn * 32;
    #pragma unroll
    for (int mi = 0; mi < 4; mi++) {
        #pragma unroll
        for (int ni = 0; ni < 4; ni++) {
            #pragma unroll
            for (int c = 0; c < 4; c++) {
                const int n_loc = nb + ni * 8 + (lane & 3) * 2 + (c & 1);
                const int m     = mb + mi * 16 + (lane >> 2) + (c >> 1) * 8;
                float v = fmaxf(acc[mi][ni][c] + b1_s[n_loc], 0.0f);
                lmax = fmaxf(lmax, v);
                const int sl = slot_s[n_loc];
                if (sl >= 0) g_hT2[(size_t)sl * B_ + m] = v;
            }
        }
    }
    #pragma unroll
    for (int o = 16; o; o >>= 1) lmax = fmaxf(lmax, __shfl_xor_sync(0xFFFFFFFFu, lmax, o));
    if (lane == 0) atomicMax(&g_maxbits, __float_as_uint(lmax));
}

// ---------------------------------------------------------------------------
// Layer 2 partial sums over compacted columns (exact integer accumulation).
// ---------------------------------------------------------------------------
__global__ void __launch_bounds__(512)
l2_partial_kernel() {
    const int m   = blockIdx.x * 512 + threadIdx.x;
    const int nn  = g_nnzc;
    const int per = (nn + NSPL - 1) / NSPL;
    const int c0  = blockIdx.y * per;
    const int c1  = min(c0 + per, nn);

    const float scale = 127.0f / __uint_as_float(g_maxbits);

    float acc[DOUT];
    #pragma unroll
    for (int o = 0; o < DOUT; o++) acc[o] = 0.0f;

    for (int c = c0; c < c1; c++) {
        const unsigned cw = __ldg(g_nzw2 + c);
        const float    v  = __ldg(g_hT2 + (size_t)c * B_ + m);
        const float    q  = fminf(rintf(v * scale), 127.0f);
        #pragma unroll
        for (int o = 0; o < DOUT; o++) {
            if (cw & (1u << o))        acc[o] += q;
            if (cw & (1u << (16 + o))) acc[o] -= q;
        }
    }
    #pragma unroll
    for (int o = 0; o < DOUT; o++)
        if (acc[o] != 0.0f) atomicAdd(&g_logits[m * 16 + o], acc[o]);
}

__global__ void __launch_bounds__(256)
softmax_kernel(const float* __restrict__ b2, float* __restrict__ out) {
    const int m = blockIdx.x * 256 + threadIdx.x;
    const float inv = __uint_as_float(g_maxbits) * (1.0f / 127.0f);

    float l[DOUT];
    float mx = -1e30f;
    #pragma unroll
    for (int o = 0; o < DOUT; o++) {
        l[o] = g_logits[m * 16 + o] * inv + __ldg(b2 + o);
        mx = fmaxf(mx, l[o]);
    }
    float s = 0.0f;
    #pragma unroll
    for (int o = 0; o < DOUT; o++) s += expf(l[o] - mx);
    const float ls = logf(s);
    #pragma unroll
    for (int o = 0; o < DOUT; o++) out[(size_t)m * DOUT + o] = l[o] - mx - ls;
}

// ---------------------------------------------------------------------------
extern "C" void kernel_launch(void* const* d_in, const int* in_sizes, int n_in,
                              void* d_out, int out_size) {
    const float* x  = (const float*)d_in[0];
    const float* w1 = (const float*)d_in[1];
    const float* b1 = (const float*)d_in[2];
    const float* w2 = (const float*)d_in[3];
    const float* b2 = (const float*)d_in[4];
    float* out = (float*)d_out;

    cudaFuncSetAttribute(gemm_mma_kernel,
                         cudaFuncAttributeMaxDynamicSharedMemorySize, GSMEM);

    init_kernel<<<1, 1>>>();
    l2init_kernel<<<(B_ * 16) / 512, 512>>>();
    build_w2col_kernel<<<DH / 256, 256>>>(w2);
    convert_x_kernel<<<(B_ * KE) / 256, 256>>>(x);
    convert_w1_kernel<<<(DH * KE) / 256, 256>>>(w1);
    gemm_mma_kernel<<<dim3(B_ / BM, DH / BN), 512, GSMEM>>>(b1);
    l2_partial_kernel<<<dim3(B_ / 512, NSPL), 512>>>();
    softmax_kernel<<<B_ / 256, 256>>>(b2, out);
}

// round 9
// speedup vs baseline: 1.0924x; 1.0924x over previous
#include <cuda_runtime.h>
#include <cuda_fp16.h>
#include <math.h>
#include <stdint.h>

// ---------------------------------------------------------------------------
// SmallMLP ternary forward, v6: HMMA fp16 GEMM1, exact 2-way split,
// 64x64 warp tiles (LDS-traffic-optimal for the legacy mma.sync path).
//   x = hi + lo (fp16 pair: 22 mantissa bits -> residual 2^-22, negligible)
//   h = relu([hi|lo] @ [tern(w1)|tern(w1)]^T + b1)   (K_eff = 1568 = 49*32)
//   s = 127/max(h);  logits = (round(h*s) @ tern(w2)^T)/s + b2;  log_softmax
// tcgen05 unavailable: harness PTX target is compute_103 (no 'a' suffix).
// ---------------------------------------------------------------------------

#define B_    8192
#define DIN   784
#define DH    4096
#define DOUT  10

#define KE    1568          // 2*784, 49 chunks of 32
#define NIT   49
#define BM    128
#define BN    256
#define BK    32
#define PITCH 80            // SMEM row pitch bytes (16B-aligned, conflict-free ldmatrix)
#define A_STG (BM * PITCH)  // 10240
#define B_STG (BN * PITCH)  // 20480
#define STG_SZ (A_STG + B_STG)
#define NSTG  4
#define GSMEM (NSTG * STG_SZ)   // 122880 bytes

#define NSPL  16

// Scratch (device globals: allocation-free rule)
__device__ __half g_A[(size_t)B_ * KE];    // [m][k] split-stacked fp16
__device__ __half g_Bw[(size_t)DH * KE];   // [n][k] ternary fp16 (dup halves)
__device__ float    g_hT2[(size_t)DH * B_];
__device__ int      g_slot[DH];
__device__ unsigned g_nzw2[DH];
__device__ int      g_nnzc;
__device__ float    g_logits[B_ * 16];
__device__ unsigned g_maxbits;

// ------------------------------ asm helpers -------------------------------
__device__ __forceinline__ uint32_t smem_u32(const void* p) {
    uint32_t a;
    asm("{ .reg .u64 t; cvta.to.shared.u64 t, %1; cvt.u32.u64 %0, t; }" : "=r"(a) : "l"(p));
    return a;
}
__device__ __forceinline__ void cp16(uint32_t dst, const void* src) {
    asm volatile("cp.async.cg.shared.global [%0], [%1], 16;" :: "r"(dst), "l"(src));
}
__device__ __forceinline__ void cp_commit() { asm volatile("cp.async.commit_group;" ::: "memory"); }
template<int N> __device__ __forceinline__ void cp_wait() {
    asm volatile("cp.async.wait_group %0;" :: "n"(N) : "memory");
}
__device__ __forceinline__ void ldm4(uint32_t* r, uint32_t addr) {
    asm volatile("ldmatrix.sync.aligned.m8n8.x4.shared.b16 {%0,%1,%2,%3}, [%4];"
                 : "=r"(r[0]), "=r"(r[1]), "=r"(r[2]), "=r"(r[3]) : "r"(addr));
}
__device__ __forceinline__ void mma_f16(float* d, const uint32_t* a, uint32_t b0, uint32_t b1) {
    asm volatile("mma.sync.aligned.m16n8k16.row.col.f32.f16.f16.f32 "
                 "{%0,%1,%2,%3}, {%4,%5,%6,%7}, {%8,%9}, {%0,%1,%2,%3};"
                 : "+f"(d[0]), "+f"(d[1]), "+f"(d[2]), "+f"(d[3])
                 : "r"(a[0]), "r"(a[1]), "r"(a[2]), "r"(a[3]), "r"(b0), "r"(b1));
}

// ------------------------------ small kernels ------------------------------
__global__ void init_kernel() { g_maxbits = 0u; g_nnzc = 0; }

__global__ void l2init_kernel() { g_logits[blockIdx.x * 512 + threadIdx.x] = 0.0f; }

// x -> split-stacked fp16: [m][k] = hi, [m][784+k] = lo. One read, two writes.
__global__ void __launch_bounds__(256)
convert_x_kernel(const float* __restrict__ x) {
    const int m = blockIdx.x;
    const int t = threadIdx.x;
    if (t >= 196) return;
    float4 v = ((const float4*)x)[m * 196 + t];
    __half h0 = __float2half(v.x), h1 = __float2half(v.y);
    __half h2 = __float2half(v.z), h3 = __float2half(v.w);
    __half l0 = __float2half(v.x - __half2float(h0));
    __half l1 = __float2half(v.y - __half2float(h1));
    __half l2 = __float2half(v.z - __half2float(h2));
    __half l3 = __float2half(v.w - __half2float(h3));
    __half2* hi = (__half2*)(g_A + (size_t)m * KE + t * 4);
    __half2* lo = (__half2*)(g_A + (size_t)m * KE + DIN + t * 4);
    hi[0] = __halves2half2(h0, h1); hi[1] = __halves2half2(h2, h3);
    lo[0] = __halves2half2(l0, l1); lo[1] = __halves2half2(l2, l3);
}

// w1 -> ternary fp16, duplicated across the two K halves.
__global__ void __launch_bounds__(256)
convert_w1_kernel(const float* __restrict__ w1) {
    const int n = blockIdx.x;
    const int t = threadIdx.x;
    if (t >= 196) return;
    float4 v = ((const float4*)w1)[n * 196 + t];
    const __half one = __float2half(1.0f), mone = __float2half(-1.0f), zero = __float2half(0.0f);
    __half t0 = (v.x > 0.1f) ? one : ((v.x < -0.1f) ? mone : zero);
    __half t1 = (v.y > 0.1f) ? one : ((v.y < -0.1f) ? mone : zero);
    __half t2 = (v.z > 0.1f) ? one : ((v.z < -0.1f) ? mone : zero);
    __half t3 = (v.w > 0.1f) ? one : ((v.w < -0.1f) ? mone : zero);
    __half2 p0 = __halves2half2(t0, t1), p1 = __halves2half2(t2, t3);
    __half2* d0 = (__half2*)(g_Bw + (size_t)n * KE + t * 4);
    __half2* d1 = (__half2*)(g_Bw + (size_t)n * KE + DIN + t * 4);
    d0[0] = p0; d0[1] = p1;
    d1[0] = p0; d1[1] = p1;
}

// Packed ternary COLUMNS of w2; compact the nonzero columns.
__global__ void build_w2col_kernel(const float* __restrict__ w2) {
    int n = blockIdx.x * 256 + threadIdx.x;
    if (n >= DH) return;
    unsigned cw = 0;
    #pragma unroll
    for (int o = 0; o < DOUT; o++) {
        float w = w2[(size_t)o * DH + n];
        if (w >  0.1f) cw |= 1u << o;
        if (w < -0.1f) cw |= 1u << (16 + o);
    }
    if (cw) {
        int p = atomicAdd(&g_nnzc, 1);
        g_nzw2[p] = cw;
        g_slot[n] = p;
    } else {
        g_slot[n] = -1;
    }
}

// ---------------------------------------------------------------------------
// HMMA GEMM: BM=128 x BN=256, BK=32, 256 threads (8 warps, warp tile 64x64),
// 4-stage cp.async pipeline. Fragment LDS traffic: 64KB per 2.1 MFLOP iter.
// ---------------------------------------------------------------------------
__device__ __forceinline__ void load_stage(uint32_t sa, uint32_t sb, int j,
                                           int m0, int n0, int tid) {
    const char* Ag = (const char*)g_A;
    const char* Bg = (const char*)g_Bw;
    const size_t koff = (size_t)j * (BK * 2);          // 64 bytes per chunk
    #pragma unroll
    for (int it = 0; it < 2; it++) {                   // A: 512 x 16B chunks
        int q = tid + it * 256;
        int r = q >> 2, c = q & 3;
        cp16(sa + r * PITCH + c * 16,
             Ag + (size_t)(m0 + r) * (KE * 2) + koff + c * 16);
    }
    #pragma unroll
    for (int it = 0; it < 4; it++) {                   // B: 1024 x 16B chunks
        int q = tid + it * 256;
        int r = q >> 2, c = q & 3;
        cp16(sb + r * PITCH + c * 16,
             Bg + (size_t)(n0 + r) * (KE * 2) + koff + c * 16);
    }
}

__global__ void __launch_bounds__(256, 1)
gemm_mma_kernel(const float* __restrict__ b1) {
    extern __shared__ char smraw[];
    const uint32_t sbase = smem_u32(smraw);
    __shared__ int   slot_s[BN];
    __shared__ float b1_s[BN];

    const int tid  = threadIdx.x;
    const int lane = tid & 31;
    const int wid  = tid >> 5;
    const int wm   = wid & 1;       // 2 m-warps (64 rows each)
    const int wn   = wid >> 1;      // 4 n-warps (64 cols each)
    const int m0   = blockIdx.x * BM;
    const int n0   = blockIdx.y * BN;

    slot_s[tid] = g_slot[n0 + tid];
    b1_s[tid]   = __ldg(b1 + n0 + tid);

    // prologue: 3 stages in flight
    #pragma unroll
    for (int s = 0; s < 3; s++) {
        uint32_t st = sbase + s * STG_SZ;
        load_stage(st, st + A_STG, s, m0, n0, tid);
        cp_commit();
    }

    float acc[4][8][4];
    #pragma unroll
    for (int mi = 0; mi < 4; mi++)
        #pragma unroll
        for (int nj = 0; nj < 8; nj++)
            #pragma unroll
            for (int c = 0; c < 4; c++) acc[mi][nj][c] = 0.0f;

    const uint32_t a_off = (wm * 64 + (lane & 15)) * PITCH + (lane >> 4) * 16;
    const uint32_t b_off = (wn * 64 + (lane & 15)) * PITCH + (lane >> 4) * 16;

    for (int j = 0; j < NIT; j++) {
        if (j + 2 < NIT)      cp_wait<2>();
        else if (j + 1 < NIT) cp_wait<1>();
        else                  cp_wait<0>();
        __syncthreads();

        if (j + 3 < NIT) {   // buffer (j+3)&3 == (j-1)&3 is free past the barrier
            uint32_t st = sbase + ((j + 3) & 3) * STG_SZ;
            load_stage(st, st + A_STG, j + 3, m0, n0, tid);
            cp_commit();
        }

        const uint32_t sa = sbase + (j & 3) * STG_SZ;
        const uint32_t sb = sa + A_STG;

        #pragma unroll
        for (int ks = 0; ks < 2; ks++) {
            uint32_t af[4][4];
            #pragma unroll
            for (int mi = 0; mi < 4; mi++)
                ldm4(af[mi], sa + a_off + mi * 16 * PITCH + ks * 32);
            uint32_t bf[4][4];
            #pragma unroll
            for (int nb = 0; nb < 4; nb++)
                ldm4(bf[nb], sb + b_off + nb * 16 * PITCH + ks * 32);
            #pragma unroll
            for (int mi = 0; mi < 4; mi++) {
                #pragma unroll
                for (int nb = 0; nb < 4; nb++) {
                    mma_f16(acc[mi][2 * nb],     af[mi], bf[nb][0], bf[nb][2]);
                    mma_f16(acc[mi][2 * nb + 1], af[mi], bf[nb][1], bf[nb][3]);
                }
            }
        }
    }

    // ---- epilogue: bias + relu + global max + compacted transposed store
    float lmax = 0.0f;
    const int mb = m0 + wm * 64;
    const int nb = wn * 64;
    #pragma unroll
    for (int mi = 0; mi < 4; mi++) {
        #pragma unroll
        for (int nj = 0; nj < 8; nj++) {
            #pragma unroll
            for (int c = 0; c < 4; c++) {
                const int n_loc = nb + nj * 8 + (lane & 3) * 2 + (c & 1);
                const int m     = mb + mi * 16 + (lane >> 2) + (c >> 1) * 8;
                float v = fmaxf(acc[mi][nj][c] + b1_s[n_loc], 0.0f);
                lmax = fmaxf(lmax, v);
                const int sl = slot_s[n_loc];
                if (sl >= 0) g_hT2[(size_t)sl * B_ + m] = v;
            }
        }
    }
    #pragma unroll
    for (int o = 16; o; o >>= 1) lmax = fmaxf(lmax, __shfl_xor_sync(0xFFFFFFFFu, lmax, o));
    if (lane == 0) atomicMax(&g_maxbits, __float_as_uint(lmax));
}

// ---------------------------------------------------------------------------
// Layer 2 partial sums over compacted columns (exact integer accumulation).
// ---------------------------------------------------------------------------
__global__ void __launch_bounds__(512)
l2_partial_kernel() {
    const int m   = blockIdx.x * 512 + threadIdx.x;
    const int nn  = g_nnzc;
    const int per = (nn + NSPL - 1) / NSPL;
    const int c0  = blockIdx.y * per;
    const int c1  = min(c0 + per, nn);

    const float scale = 127.0f / __uint_as_float(g_maxbits);

    float acc[DOUT];
    #pragma unroll
    for (int o = 0; o < DOUT; o++) acc[o] = 0.0f;

    for (int c = c0; c < c1; c++) {
        const unsigned cw = __ldg(g_nzw2 + c);
        const float    v  = __ldg(g_hT2 + (size_t)c * B_ + m);
        const float    q  = fminf(rintf(v * scale), 127.0f);
        #pragma unroll
        for (int o = 0; o < DOUT; o++) {
            if (cw & (1u << o))        acc[o] += q;
            if (cw & (1u << (16 + o))) acc[o] -= q;
        }
    }
    #pragma unroll
    for (int o = 0; o < DOUT; o++)
        if (acc[o] != 0.0f) atomicAdd(&g_logits[m * 16 + o], acc[o]);
}

__global__ void __launch_bounds__(256)
softmax_kernel(const float* __restrict__ b2, float* __restrict__ out) {
    const int m = blockIdx.x * 256 + threadIdx.x;
    const float inv = __uint_as_float(g_maxbits) * (1.0f / 127.0f);

    float l[DOUT];
    float mx = -1e30f;
    #pragma unroll
    for (int o = 0; o < DOUT; o++) {
        l[o] = g_logits[m * 16 + o] * inv + __ldg(b2 + o);
        mx = fmaxf(mx, l[o]);
    }
    float s = 0.0f;
    #pragma unroll
    for (int o = 0; o < DOUT; o++) s += expf(l[o] - mx);
    const float ls = logf(s);
    #pragma unroll
    for (int o = 0; o < DOUT; o++) out[(size_t)m * DOUT + o] = l[o] - mx - ls;
}

// ---------------------------------------------------------------------------
extern "C" void kernel_launch(void* const* d_in, const int* in_sizes, int n_in,
                              void* d_out, int out_size) {
    const float* x  = (const float*)d_in[0];
    const float* w1 = (const float*)d_in[1];
    const float* b1 = (const float*)d_in[2];
    const float* w2 = (const float*)d_in[3];
    const float* b2 = (const float*)d_in[4];
    float* out = (float*)d_out;

    cudaFuncSetAttribute(gemm_mma_kernel,
                         cudaFuncAttributeMaxDynamicSharedMemorySize, GSMEM);

    init_kernel<<<1, 1>>>();
    l2init_kernel<<<(B_ * 16) / 512, 512>>>();
    build_w2col_kernel<<<DH / 256, 256>>>(w2);
    convert_x_kernel<<<B_, 256>>>(x);
    convert_w1_kernel<<<DH, 256>>>(w1);
    gemm_mma_kernel<<<dim3(B_ / BM, DH / BN), 256, GSMEM>>>(b1);
    l2_partial_kernel<<<dim3(B_ / 512, NSPL), 512>>>();
    softmax_kernel<<<B_ / 256, 256>>>(b2, out);
}